// round 14
// baseline (speedup 1.0000x reference)
#include <cuda_runtime.h>
#include <cuda_bf16.h>
#include <cstdint>

#define B_    4
#define C_    256
#define H_    80
#define W_    80
#define HW    6400
#define K2    9
#define KDIM  2304
#define COUT  256
#define NCHUNK 72          // 9 taps * 8 channel-groups of 32
#define BROW  20           // u32 words per row (80 B stride, 16 used)

// ---------------- device scratch ----------------
__device__ float    g_xnhwc[B_ * HW * C_];          // x in NHWC
__device__ uint4    g_wA[NCHUNK * 2 * 16 * 2 * 32]; // conv-w fragments (hi/lo)
__device__ uint4    g_oA[NCHUNK * 2 * 2 * 2 * 32];  // offset-w fragments (hi/lo, M=32)
__device__ float4   g_twgt[B_ * K2 * HW];           // bilinear weights * validity
__device__ int4     g_tidx[B_ * K2 * HW];           // clamped NHWC bases

// ---------------- mma helpers ----------------
__device__ __forceinline__ void mma16816(float* d, const uint32_t* a, const uint32_t* b) {
    asm volatile(
        "mma.sync.aligned.m16n8k16.row.col.f32.bf16.bf16.f32 "
        "{%0,%1,%2,%3}, {%4,%5,%6,%7}, {%8,%9}, {%0,%1,%2,%3};"
        : "+f"(d[0]), "+f"(d[1]), "+f"(d[2]), "+f"(d[3])
        : "r"(a[0]), "r"(a[1]), "r"(a[2]), "r"(a[3]), "r"(b[0]), "r"(b[1]));
}

__device__ __forceinline__ void ldsm4(uint32_t* r, uint32_t addr) {
    asm volatile("ldmatrix.sync.aligned.m8n8.x4.shared.b16 {%0,%1,%2,%3}, [%4];"
                 : "=r"(r[0]), "=r"(r[1]), "=r"(r[2]), "=r"(r[3]) : "r"(addr));
}

__device__ __forceinline__ uint32_t pack_bf16(float lo_v, float hi_v) {
    __nv_bfloat162 h;
    h.x = __float2bfloat16(lo_v);
    h.y = __float2bfloat16(hi_v);
    return *(uint32_t*)&h;
}

// ---------------- kernel 1: NCHW -> NHWC transpose -------------------------
__global__ void k_transpose(const float* __restrict__ x) {
    __shared__ float tile[32][33];
    int b   = blockIdx.z;
    int hw0 = blockIdx.x * 32;
    int c0  = blockIdx.y * 32;
    int tx = threadIdx.x, ty = threadIdx.y;
    const float* xb = x + b * C_ * HW;
    #pragma unroll
    for (int i = 0; i < 32; i += 8)
        tile[ty + i][tx] = xb[(c0 + ty + i) * HW + hw0 + tx];
    __syncthreads();
    float* ob = g_xnhwc + b * HW * C_;
    #pragma unroll
    for (int i = 0; i < 32; i += 8)
        ob[(hw0 + ty + i) * C_ + c0 + tx] = tile[tx][ty + i];
}

// ---------------- kernel 2: fragment-pack conv-w and offset-w --------------
#define WA_BLOCKS 576   // 147456 / 256
__global__ void k_prep(const float* __restrict__ ow, const float* __restrict__ cw) {
    int blk = blockIdx.x;
    if (blk < WA_BLOCKS) {
        int e = blk * 256 + threadIdx.x;
        int lane = e & 31;
        int s    = (e >> 5) & 1;
        int mt   = (e >> 6) & 15;
        int term = (e >> 10) & 1;
        int q    = e >> 11;
        int tap   = q >> 3;
        int cbase = (q & 7) * 32;
        uint32_t r[4];
        #pragma unroll
        for (int rr = 0; rr < 4; rr++) {
            int m  = mt * 16 + (lane >> 2) + ((rr & 1) << 3);
            int kl = s * 16 + (lane & 3) * 2 + ((rr >> 1) << 3);
            float w0 = __ldg(cw + m * KDIM + (cbase + kl) * 9 + tap);
            float w1 = __ldg(cw + m * KDIM + (cbase + kl + 1) * 9 + tap);
            if (term) {
                w0 -= __bfloat162float(__float2bfloat16(w0));
                w1 -= __bfloat162float(__float2bfloat16(w1));
            }
            r[rr] = pack_bf16(w0, w1);
        }
        g_wA[e] = make_uint4(r[0], r[1], r[2], r[3]);
    } else {
        int e = (blk - WA_BLOCKS) * 256 + threadIdx.x;   // < 18432
        if (e < NCHUNK * 2 * 2 * 2 * 32) {
            int lane = e & 31;
            int s    = (e >> 5) & 1;
            int mt   = (e >> 6) & 1;
            int term = (e >> 7) & 1;
            int q    = e >> 8;
            int tap   = q >> 3;
            int cbase = (q & 7) * 32;
            uint32_t r[4];
            #pragma unroll
            for (int rr = 0; rr < 4; rr++) {
                int m  = mt * 16 + (lane >> 2) + ((rr & 1) << 3);
                int kl = s * 16 + (lane & 3) * 2 + ((rr >> 1) << 3);
                float w0 = 0.f, w1 = 0.f;
                if (m < 18) {
                    w0 = __ldg(ow + m * KDIM + (cbase + kl) * 9 + tap);
                    w1 = __ldg(ow + m * KDIM + (cbase + kl + 1) * 9 + tap);
                }
                if (term) {
                    w0 -= __bfloat162float(__float2bfloat16(w0));
                    w1 -= __bfloat162float(__float2bfloat16(w1));
                }
                r[rr] = pack_bf16(w0, w1);
            }
            g_oA[e] = make_uint4(r[0], r[1], r[2], r[3]);
        }
    }
}

// ---------------- kernel 3: offset conv via mma + tap metadata -------------
__global__ void __launch_bounds__(256) k_offset(const float* __restrict__ off_b) {
    __shared__ uint32_t sB[2][64 * BROW];
    __shared__ float offs[64][19];

    int tid  = threadIdx.x;
    int wid  = tid >> 5, lane = tid & 31;
    int blk  = blockIdx.x;                 // 0..399
    int b    = blk / (HW / 64);
    int hw0  = (blk % (HW / 64)) * 64;

    const float4* xb4 = (const float4*)(g_xnhwc + (size_t)b * HW * C_);

    int px = tid >> 2, cq = tid & 3;
    int gpx = hw0 + px;
    int py = gpx / W_, pxx = gpx % W_;

    int mat = lane >> 3, mrow = lane & 7;
    int jd  = mat >> 1, kh = mat & 1;
    uint32_t lmB = (uint32_t)(((wid * 16 + jd * 8 + mrow) * BROW + kh * 4) * 4);
    uint32_t sb0 = (uint32_t)__cvta_generic_to_shared(&sB[0][0]);
    uint32_t sb1 = (uint32_t)__cvta_generic_to_shared(&sB[1][0]);

    float acc[2][2][4];
    #pragma unroll
    for (int mt = 0; mt < 2; mt++)
        #pragma unroll
        for (int j = 0; j < 2; j++)
            #pragma unroll
            for (int r = 0; r < 4; r++) acc[mt][j][r] = 0.f;

    for (int q = 0; q < NCHUNK; q++) {
        int tap = q >> 3, cg = q & 7;
        int dy = tap / 3 - 1, dx = tap % 3 - 1;
        int ny = py + dy, nx = pxx + dx;
        bool valid = (ny >= 0 && ny < H_ && nx >= 0 && nx < W_);
        const float4* src = xb4 + (((ny * W_ + nx) * C_ + cg * 32 + cq * 8) >> 2);

        __syncthreads();
        #pragma unroll
        for (int cc = 0; cc < 2; cc++) {
            float4 v = valid ? __ldg(src + cc)
                             : make_float4(0.f, 0.f, 0.f, 0.f);
            uint32_t h01 = pack_bf16(v.x, v.y);
            uint32_t h23 = pack_bf16(v.z, v.w);
            __nv_bfloat162 hh01 = *(__nv_bfloat162*)&h01;
            __nv_bfloat162 hh23 = *(__nv_bfloat162*)&h23;
            float lx = v.x - __bfloat162float(hh01.x);
            float ly = v.y - __bfloat162float(hh01.y);
            float lz = v.z - __bfloat162float(hh23.x);
            float lw = v.w - __bfloat162float(hh23.y);
            int word = px * BROW + cq * 4 + cc * 2;
            *(uint2*)&sB[0][word] = make_uint2(h01, h23);
            *(uint2*)&sB[1][word] = make_uint2(pack_bf16(lx, ly), pack_bf16(lz, lw));
        }
        __syncthreads();

        if (wid < 4) {
            #pragma unroll
            for (int s = 0; s < 2; s++) {
                uint32_t soff = (uint32_t)(s * 32);
                uint32_t Bh[4], Bl[4];
                ldsm4(Bh, sb0 + lmB + soff);
                ldsm4(Bl, sb1 + lmB + soff);
                uint4 Ah[2], Al[2];
                #pragma unroll
                for (int mt = 0; mt < 2; mt++) {
                    Ah[mt] = __ldg(&g_oA[(((q * 2 + 0) * 2 + mt) * 2 + s) * 32 + lane]);
                    Al[mt] = __ldg(&g_oA[(((q * 2 + 1) * 2 + mt) * 2 + s) * 32 + lane]);
                }
                #pragma unroll
                for (int mt = 0; mt < 2; mt++)
                    #pragma unroll
                    for (int j = 0; j < 2; j++) {
                        mma16816(acc[mt][j], (const uint32_t*)&Ah[mt], Bh + 2 * j);
                        mma16816(acc[mt][j], (const uint32_t*)&Ah[mt], Bl + 2 * j);
                        mma16816(acc[mt][j], (const uint32_t*)&Al[mt], Bh + 2 * j);
                    }
            }
        }
    }
    __syncthreads();

    if (wid < 4) {
        #pragma unroll
        for (int mt = 0; mt < 2; mt++)
            #pragma unroll
            for (int j = 0; j < 2; j++)
                #pragma unroll
                for (int r = 0; r < 4; r++) {
                    int oc = mt * 16 + (lane >> 2) + ((r >> 1) << 3);
                    int pc = wid * 16 + j * 8 + (lane & 3) * 2 + (r & 1);
                    if (oc < 18)
                        offs[pc][oc] = acc[mt][j][r] + __ldg(off_b + oc);
                }
    }
    __syncthreads();

    for (int u = tid; u < 64 * 9; u += 256) {
        int l = u / 9, k = u % 9;
        float dyo = offs[l][2 * k], dxo = offs[l][2 * k + 1];
        int pp = hw0 + l;
        int yy = pp / W_, xx = pp % W_;
        float fy = (float)(yy + k / 3 - 1) + dyo;
        float fx = (float)(xx + k % 3 - 1) + dxo;
        float y0f = floorf(fy), x0f = floorf(fx);
        float wy = fy - y0f, wx = fx - x0f;
        int y0 = (int)y0f, x0 = (int)x0f;
        int y1 = y0 + 1,   x1 = x0 + 1;
        float vy0 = (y0 >= 0 && y0 < H_) ? 1.f : 0.f;
        float vy1 = (y1 >= 0 && y1 < H_) ? 1.f : 0.f;
        float vx0 = (x0 >= 0 && x0 < W_) ? 1.f : 0.f;
        float vx1 = (x1 >= 0 && x1 < W_) ? 1.f : 0.f;
        int cy0 = min(max(y0, 0), H_ - 1), cy1 = min(max(y1, 0), H_ - 1);
        int cx0 = min(max(x0, 0), W_ - 1), cx1 = min(max(x1, 0), W_ - 1);
        float4 wt;
        wt.x = (1.f - wy) * (1.f - wx) * vy0 * vx0;
        wt.y = (1.f - wy) * wx         * vy0 * vx1;
        wt.z = wy * (1.f - wx)         * vy1 * vx0;
        wt.w = wy * wx                 * vy1 * vx1;
        int4 id;
        id.x = (cy0 * W_ + cx0) * C_;
        id.y = (cy0 * W_ + cx1) * C_;
        id.z = (cy1 * W_ + cx0) * C_;
        id.w = (cy1 * W_ + cx1) * C_;
        int m = (b * 9 + k) * HW + pp;
        g_twgt[m] = wt;
        g_tidx[m] = id;
    }
}

// ---------------- kernel 4: warp-specialized main GEMM, paired chunks ------
// 384 threads: warps 0-7 mma (M=256 x N=64), warps 8-11 producers.
// One __syncthreads per chunk PAIR; 4-stage sB so pair t (stages {0,1} or
// {2,3}) is produced while the previous pair is consumed. Within a pair the
// producer's second-chunk LDGs overlap the first chunk's convert/store.
__global__ void __launch_bounds__(384, 1) k_main(const float* __restrict__ cb,
                                                 float* __restrict__ out) {
    __shared__ uint32_t sB[4][2][64 * BROW];   // [stage][term][pixel*20 + word]

    int tid  = threadIdx.x;
    int wid  = tid >> 5, lane = tid & 31;
    int blk  = blockIdx.x;                   // 0..399
    int b    = blk / (HW / 64);
    int hw0  = (blk % (HW / 64)) * 64;
    int b9   = b * 9;

    const float4* xb4 = (const float4*)(g_xnhwc + (size_t)b * HW * C_);

    if (wid >= 8) {
        // ================= producer warps =================
        int gtid = tid - 256;                // 0..127
        int gl8  = gtid & 7;
        int gpx  = gtid >> 3;                // 0..15
        for (int t = 0; t < NCHUNK / 2; t++) {
            #pragma unroll
            for (int sub = 0; sub < 2; sub++) {
                int nq   = 2 * t + sub;
                int nbuf = nq & 3;
                int tap = nq >> 3, cg = nq & 7;
                int cc  = cg * 32 + gl8 * 4;
                int mmb = (b9 + tap) * HW + hw0;
                // prefetch A fragments two chunks ahead
                if (nq + 2 < NCHUNK) {
                    const char* pA = (const char*)(g_wA + (nq + 2) * 2048);
                    asm volatile("prefetch.global.L1 [%0];" :: "l"(pA + gtid * 256));
                    asm volatile("prefetch.global.L1 [%0];" :: "l"(pA + gtid * 256 + 128));
                }
                #pragma unroll
                for (int pass = 0; pass < 4; pass++) {
                    int pp = gpx + pass * 16;
                    int mm = mmb + pp;
                    float4 wt = g_twgt[mm];
                    int4   id = g_tidx[mm];
                    float4 t0 = __ldg(xb4 + ((id.x + cc) >> 2));
                    float4 t1 = __ldg(xb4 + ((id.y + cc) >> 2));
                    float4 t2 = __ldg(xb4 + ((id.z + cc) >> 2));
                    float4 t3 = __ldg(xb4 + ((id.w + cc) >> 2));
                    float4 v;
                    v.x = wt.x * t0.x + wt.y * t1.x + wt.z * t2.x + wt.w * t3.x;
                    v.y = wt.x * t0.y + wt.y * t1.y + wt.z * t2.y + wt.w * t3.y;
                    v.z = wt.x * t0.z + wt.y * t1.z + wt.z * t2.z + wt.w * t3.z;
                    v.w = wt.x * t0.w + wt.y * t1.w + wt.z * t2.w + wt.w * t3.w;
                    uint32_t h01 = pack_bf16(v.x, v.y);
                    uint32_t h23 = pack_bf16(v.z, v.w);
                    __nv_bfloat162 hh01 = *(__nv_bfloat162*)&h01;
                    __nv_bfloat162 hh23 = *(__nv_bfloat162*)&h23;
                    float lx = v.x - __bfloat162float(hh01.x);
                    float ly = v.y - __bfloat162float(hh01.y);
                    float lz = v.z - __bfloat162float(hh23.x);
                    float lw = v.w - __bfloat162float(hh23.y);
                    int word = pp * BROW + gl8 * 2;
                    *(uint2*)&sB[nbuf][0][word] = make_uint2(h01, h23);
                    *(uint2*)&sB[nbuf][1][word] =
                        make_uint2(pack_bf16(lx, ly), pack_bf16(lz, lw));
                }
            }
            __syncthreads();   // pair t ready
        }
        __syncthreads();       // match consumers' final barrier
    } else {
        // ================= mma warps =================
        int wm = wid >> 1, wn = wid & 1;

        float acc[4][4][4];
        #pragma unroll
        for (int i = 0; i < 4; i++)
            #pragma unroll
            for (int j = 0; j < 4; j++)
                #pragma unroll
                for (int r = 0; r < 4; r++) acc[i][j][r] = 0.f;

        int mat = lane >> 3, mrow = lane & 7;
        int jd  = mat >> 1, kh = mat & 1;
        uint32_t lmB = ((wn * 32 + jd * 8 + mrow) * BROW + kh * 4) * 4;

        for (int t = 0; t < NCHUNK / 2; t++) {
            __syncthreads();   // wait for pair t
            #pragma unroll
            for (int sub = 0; sub < 2; sub++) {
                int q   = 2 * t + sub;
                int buf = q & 3;
                uint32_t bH = (uint32_t)__cvta_generic_to_shared(&sB[buf][0][0]);
                uint32_t bL = (uint32_t)__cvta_generic_to_shared(&sB[buf][1][0]);

                #pragma unroll
                for (int s = 0; s < 2; s++) {
                    uint32_t soff = (uint32_t)(s * 32);
                    uint32_t Bh[8], Bl[8];
                    ldsm4(Bh + 0, bH + lmB + soff);
                    ldsm4(Bh + 4, bH + lmB + soff + (uint32_t)(16 * BROW * 4));
                    ldsm4(Bl + 0, bL + lmB + soff);
                    ldsm4(Bl + 4, bL + lmB + soff + (uint32_t)(16 * BROW * 4));
                    uint4 Ah[4];
                    #pragma unroll
                    for (int i = 0; i < 4; i++)
                        Ah[i] = __ldg(&g_wA[(((q * 2 + 0) * 16 + wm * 4 + i) * 2 + s) * 32 + lane]);
                    #pragma unroll
                    for (int i = 0; i < 4; i++)
                        #pragma unroll
                        for (int j = 0; j < 4; j++)
                            mma16816(acc[i][j], (const uint32_t*)&Ah[i], Bh + 2 * j);
                    #pragma unroll
                    for (int i = 0; i < 4; i++)
                        #pragma unroll
                        for (int j = 0; j < 4; j++)
                            mma16816(acc[i][j], (const uint32_t*)&Ah[i], Bl + 2 * j);
                    #pragma unroll
                    for (int i = 0; i < 4; i++) {
                        uint4 Al = __ldg(&g_wA[(((q * 2 + 1) * 16 + wm * 4 + i) * 2 + s) * 32 + lane]);
                        #pragma unroll
                        for (int j = 0; j < 4; j++)
                            mma16816(acc[i][j], (const uint32_t*)&Al, Bh + 2 * j);
                    }
                }
            }
        }
        __syncthreads();

        int q_ = lane >> 2, t_ = lane & 3;
        #pragma unroll
        for (int i = 0; i < 4; i++) {
            int o0 = wm * 64 + i * 16 + q_;
            float bias0 = __ldg(cb + o0);
            float bias1 = __ldg(cb + o0 + 8);
            float* r0 = out + (size_t)(b * COUT + o0) * HW + hw0 + wn * 32;
            float* r1 = out + (size_t)(b * COUT + o0 + 8) * HW + hw0 + wn * 32;
            #pragma unroll
            for (int j = 0; j < 4; j++) {
                float2 s0, s1;
                s0.x = acc[i][j][0] + bias0; s0.y = acc[i][j][1] + bias0;
                s1.x = acc[i][j][2] + bias1; s1.y = acc[i][j][3] + bias1;
                *(float2*)(r0 + j * 8 + t_ * 2) = s0;
                *(float2*)(r1 + j * 8 + t_ * 2) = s1;
            }
        }
    }
}

// ---------------- launch -----------------------------------------------------
extern "C" void kernel_launch(void* const* d_in, const int* in_sizes, int n_in,
                              void* d_out, int out_size) {
    const float* x  = (const float*)d_in[0];
    const float* ow = (const float*)d_in[1];
    const float* ob = (const float*)d_in[2];
    const float* cw = (const float*)d_in[3];
    const float* cb = (const float*)d_in[4];
    float* out      = (float*)d_out;

    {
        dim3 grid(HW / 32, C_ / 32, B_);
        dim3 block(32, 8);
        k_transpose<<<grid, block>>>(x);
    }
    k_prep<<<WA_BLOCKS + (NCHUNK * 2 * 2 * 2 * 32) / 256, 256>>>(ow, cw);
    k_offset<<<B_ * (HW / 64), 256>>>(ob);

    // one CTA per (batch, 64-pixel tile): 400 CTAs
    k_main<<<B_ * (HW / 64), 384>>>(cb, out);
}

// round 15
// speedup vs baseline: 1.0180x; 1.0180x over previous
#include <cuda_runtime.h>
#include <cuda_bf16.h>
#include <cstdint>

#define B_    4
#define C_    256
#define H_    80
#define W_    80
#define HW    6400
#define K2    9
#define KDIM  2304
#define COUT  256
#define NCHUNK 72          // 9 taps * 8 channel-groups of 32
#define BROW  20           // u32 words per row (80 B stride, 16 used)

// ---------------- device scratch ----------------
__device__ float    g_xnhwc[B_ * HW * C_];          // x in NHWC
__device__ uint4    g_wA[NCHUNK * 2 * 16 * 2 * 32]; // conv-w fragments (hi/lo)
__device__ uint4    g_oA[NCHUNK * 2 * 2 * 2 * 32];  // offset-w fragments (hi/lo, M=32)
__device__ float4   g_twgt[B_ * K2 * HW];           // bilinear weights * validity
__device__ int4     g_tidx[B_ * K2 * HW];           // clamped NHWC bases

// ---------------- mma helpers ----------------
__device__ __forceinline__ void mma16816(float* d, const uint32_t* a, const uint32_t* b) {
    asm volatile(
        "mma.sync.aligned.m16n8k16.row.col.f32.bf16.bf16.f32 "
        "{%0,%1,%2,%3}, {%4,%5,%6,%7}, {%8,%9}, {%0,%1,%2,%3};"
        : "+f"(d[0]), "+f"(d[1]), "+f"(d[2]), "+f"(d[3])
        : "r"(a[0]), "r"(a[1]), "r"(a[2]), "r"(a[3]), "r"(b[0]), "r"(b[1]));
}

__device__ __forceinline__ void ldsm4(uint32_t* r, uint32_t addr) {
    asm volatile("ldmatrix.sync.aligned.m8n8.x4.shared.b16 {%0,%1,%2,%3}, [%4];"
                 : "=r"(r[0]), "=r"(r[1]), "=r"(r[2]), "=r"(r[3]) : "r"(addr));
}

__device__ __forceinline__ uint32_t pack_bf16(float lo_v, float hi_v) {
    __nv_bfloat162 h;
    h.x = __float2bfloat16(lo_v);
    h.y = __float2bfloat16(hi_v);
    return *(uint32_t*)&h;
}

// ---------------- kernel 1: merged NCHW->NHWC transpose + weight prep ------
// blocks [0,6400): transpose tiles; [6400,6976): conv-w fragments;
// [6976,7048): offset-w fragments. All independent work, one launch.
#define TP_BLOCKS 6400
#define WA_BLOCKS 576   // 147456 / 256
__global__ void __launch_bounds__(256) k_tp_prep(const float* __restrict__ x,
                                                 const float* __restrict__ ow,
                                                 const float* __restrict__ cw) {
    int blk = blockIdx.x;
    if (blk < TP_BLOCKS) {
        __shared__ float tile[32][33];
        int hwb = blk % 200;
        int cb_ = (blk / 200) & 7;
        int b   = blk / 1600;
        int hw0 = hwb * 32;
        int c0  = cb_ * 32;
        int tx = threadIdx.x & 31, ty = threadIdx.x >> 5;
        const float* xb = x + b * C_ * HW;
        #pragma unroll
        for (int i = 0; i < 32; i += 8)
            tile[ty + i][tx] = xb[(c0 + ty + i) * HW + hw0 + tx];
        __syncthreads();
        float* ob = g_xnhwc + b * HW * C_;
        #pragma unroll
        for (int i = 0; i < 32; i += 8)
            ob[(hw0 + ty + i) * C_ + c0 + tx] = tile[tx][ty + i];
    } else if (blk < TP_BLOCKS + WA_BLOCKS) {
        int e = (blk - TP_BLOCKS) * 256 + threadIdx.x;
        int lane = e & 31;
        int s    = (e >> 5) & 1;
        int mt   = (e >> 6) & 15;
        int term = (e >> 10) & 1;
        int q    = e >> 11;
        int tap   = q >> 3;
        int cbase = (q & 7) * 32;
        uint32_t r[4];
        #pragma unroll
        for (int rr = 0; rr < 4; rr++) {
            int m  = mt * 16 + (lane >> 2) + ((rr & 1) << 3);
            int kl = s * 16 + (lane & 3) * 2 + ((rr >> 1) << 3);
            float w0 = __ldg(cw + m * KDIM + (cbase + kl) * 9 + tap);
            float w1 = __ldg(cw + m * KDIM + (cbase + kl + 1) * 9 + tap);
            if (term) {
                w0 -= __bfloat162float(__float2bfloat16(w0));
                w1 -= __bfloat162float(__float2bfloat16(w1));
            }
            r[rr] = pack_bf16(w0, w1);
        }
        g_wA[e] = make_uint4(r[0], r[1], r[2], r[3]);
    } else {
        int e = (blk - TP_BLOCKS - WA_BLOCKS) * 256 + threadIdx.x;
        if (e < NCHUNK * 2 * 2 * 2 * 32) {
            int lane = e & 31;
            int s    = (e >> 5) & 1;
            int mt   = (e >> 6) & 1;
            int term = (e >> 7) & 1;
            int q    = e >> 8;
            int tap   = q >> 3;
            int cbase = (q & 7) * 32;
            uint32_t r[4];
            #pragma unroll
            for (int rr = 0; rr < 4; rr++) {
                int m  = mt * 16 + (lane >> 2) + ((rr & 1) << 3);
                int kl = s * 16 + (lane & 3) * 2 + ((rr >> 1) << 3);
                float w0 = 0.f, w1 = 0.f;
                if (m < 18) {
                    w0 = __ldg(ow + m * KDIM + (cbase + kl) * 9 + tap);
                    w1 = __ldg(ow + m * KDIM + (cbase + kl + 1) * 9 + tap);
                }
                if (term) {
                    w0 -= __bfloat162float(__float2bfloat16(w0));
                    w1 -= __bfloat162float(__float2bfloat16(w1));
                }
                r[rr] = pack_bf16(w0, w1);
            }
            g_oA[e] = make_uint4(r[0], r[1], r[2], r[3]);
        }
    }
}

// ---------------- kernel 2: offset conv via mma + tap metadata -------------
__global__ void __launch_bounds__(256) k_offset(const float* __restrict__ off_b) {
    __shared__ uint32_t sB[2][64 * BROW];
    __shared__ float offs[64][19];

    int tid  = threadIdx.x;
    int wid  = tid >> 5, lane = tid & 31;
    int blk  = blockIdx.x;                 // 0..399
    int b    = blk / (HW / 64);
    int hw0  = (blk % (HW / 64)) * 64;

    const float4* xb4 = (const float4*)(g_xnhwc + (size_t)b * HW * C_);

    int px = tid >> 2, cq = tid & 3;
    int gpx = hw0 + px;
    int py = gpx / W_, pxx = gpx % W_;

    int mat = lane >> 3, mrow = lane & 7;
    int jd  = mat >> 1, kh = mat & 1;
    uint32_t lmB = (uint32_t)(((wid * 16 + jd * 8 + mrow) * BROW + kh * 4) * 4);
    uint32_t sb0 = (uint32_t)__cvta_generic_to_shared(&sB[0][0]);
    uint32_t sb1 = (uint32_t)__cvta_generic_to_shared(&sB[1][0]);

    float acc[2][2][4];
    #pragma unroll
    for (int mt = 0; mt < 2; mt++)
        #pragma unroll
        for (int j = 0; j < 2; j++)
            #pragma unroll
            for (int r = 0; r < 4; r++) acc[mt][j][r] = 0.f;

    for (int q = 0; q < NCHUNK; q++) {
        int tap = q >> 3, cg = q & 7;
        int dy = tap / 3 - 1, dx = tap % 3 - 1;
        int ny = py + dy, nx = pxx + dx;
        bool valid = (ny >= 0 && ny < H_ && nx >= 0 && nx < W_);
        const float4* src = xb4 + (((ny * W_ + nx) * C_ + cg * 32 + cq * 8) >> 2);

        __syncthreads();
        #pragma unroll
        for (int cc = 0; cc < 2; cc++) {
            float4 v = valid ? __ldg(src + cc)
                             : make_float4(0.f, 0.f, 0.f, 0.f);
            uint32_t h01 = pack_bf16(v.x, v.y);
            uint32_t h23 = pack_bf16(v.z, v.w);
            __nv_bfloat162 hh01 = *(__nv_bfloat162*)&h01;
            __nv_bfloat162 hh23 = *(__nv_bfloat162*)&h23;
            float lx = v.x - __bfloat162float(hh01.x);
            float ly = v.y - __bfloat162float(hh01.y);
            float lz = v.z - __bfloat162float(hh23.x);
            float lw = v.w - __bfloat162float(hh23.y);
            int word = px * BROW + cq * 4 + cc * 2;
            *(uint2*)&sB[0][word] = make_uint2(h01, h23);
            *(uint2*)&sB[1][word] = make_uint2(pack_bf16(lx, ly), pack_bf16(lz, lw));
        }
        __syncthreads();

        if (wid < 4) {
            #pragma unroll
            for (int s = 0; s < 2; s++) {
                uint32_t soff = (uint32_t)(s * 32);
                uint32_t Bh[4], Bl[4];
                ldsm4(Bh, sb0 + lmB + soff);
                ldsm4(Bl, sb1 + lmB + soff);
                uint4 Ah[2], Al[2];
                #pragma unroll
                for (int mt = 0; mt < 2; mt++) {
                    Ah[mt] = __ldg(&g_oA[(((q * 2 + 0) * 2 + mt) * 2 + s) * 32 + lane]);
                    Al[mt] = __ldg(&g_oA[(((q * 2 + 1) * 2 + mt) * 2 + s) * 32 + lane]);
                }
                #pragma unroll
                for (int mt = 0; mt < 2; mt++)
                    #pragma unroll
                    for (int j = 0; j < 2; j++) {
                        mma16816(acc[mt][j], (const uint32_t*)&Ah[mt], Bh + 2 * j);
                        mma16816(acc[mt][j], (const uint32_t*)&Ah[mt], Bl + 2 * j);
                        mma16816(acc[mt][j], (const uint32_t*)&Al[mt], Bh + 2 * j);
                    }
            }
        }
    }
    __syncthreads();

    if (wid < 4) {
        #pragma unroll
        for (int mt = 0; mt < 2; mt++)
            #pragma unroll
            for (int j = 0; j < 2; j++)
                #pragma unroll
                for (int r = 0; r < 4; r++) {
                    int oc = mt * 16 + (lane >> 2) + ((r >> 1) << 3);
                    int pc = wid * 16 + j * 8 + (lane & 3) * 2 + (r & 1);
                    if (oc < 18)
                        offs[pc][oc] = acc[mt][j][r] + __ldg(off_b + oc);
                }
    }
    __syncthreads();

    for (int u = tid; u < 64 * 9; u += 256) {
        int l = u / 9, k = u % 9;
        float dyo = offs[l][2 * k], dxo = offs[l][2 * k + 1];
        int pp = hw0 + l;
        int yy = pp / W_, xx = pp % W_;
        float fy = (float)(yy + k / 3 - 1) + dyo;
        float fx = (float)(xx + k % 3 - 1) + dxo;
        float y0f = floorf(fy), x0f = floorf(fx);
        float wy = fy - y0f, wx = fx - x0f;
        int y0 = (int)y0f, x0 = (int)x0f;
        int y1 = y0 + 1,   x1 = x0 + 1;
        float vy0 = (y0 >= 0 && y0 < H_) ? 1.f : 0.f;
        float vy1 = (y1 >= 0 && y1 < H_) ? 1.f : 0.f;
        float vx0 = (x0 >= 0 && x0 < W_) ? 1.f : 0.f;
        float vx1 = (x1 >= 0 && x1 < W_) ? 1.f : 0.f;
        int cy0 = min(max(y0, 0), H_ - 1), cy1 = min(max(y1, 0), H_ - 1);
        int cx0 = min(max(x0, 0), W_ - 1), cx1 = min(max(x1, 0), W_ - 1);
        float4 wt;
        wt.x = (1.f - wy) * (1.f - wx) * vy0 * vx0;
        wt.y = (1.f - wy) * wx         * vy0 * vx1;
        wt.z = wy * (1.f - wx)         * vy1 * vx0;
        wt.w = wy * wx                 * vy1 * vx1;
        int4 id;
        id.x = (cy0 * W_ + cx0) * C_;
        id.y = (cy0 * W_ + cx1) * C_;
        id.z = (cy1 * W_ + cx0) * C_;
        id.w = (cy1 * W_ + cx1) * C_;
        int m = (b * 9 + k) * HW + pp;
        g_twgt[m] = wt;
        g_tidx[m] = id;
    }
}

// ---------------- kernel 3: warp-specialized main GEMM (R12 + early Al) ----
// Warps 0-7 mma (M=256 x N=64), warps 8-11 producers (tap-outer metadata
// hoist + A prefetch). Consumer issues Ah AND Al loads at the top of each
// s-slice so their latency hides under the first two mma terms.
__global__ void __launch_bounds__(384, 1) k_main(const float* __restrict__ cb,
                                                 float* __restrict__ out) {
    __shared__ uint32_t sB[2][2][64 * BROW];   // [buf][term][pixel*20 + word]

    int tid  = threadIdx.x;
    int wid  = tid >> 5, lane = tid & 31;
    int blk  = blockIdx.x;                   // 0..399
    int b    = blk / (HW / 64);
    int hw0  = (blk % (HW / 64)) * 64;
    int b9   = b * 9;

    const float4* xb4 = (const float4*)(g_xnhwc + (size_t)b * HW * C_);

    if (wid >= 8) {
        // ================= producer warps =================
        int gtid = tid - 256;                // 0..127
        int gl8  = gtid & 7;
        int gpx  = gtid >> 3;                // 0..15
        for (int tap = 0; tap < 9; tap++) {
            int mmb = (b9 + tap) * HW + hw0;
            float4 wt[4]; int4 id[4];
            #pragma unroll
            for (int pass = 0; pass < 4; pass++) {
                int mm = mmb + gpx + pass * 16;
                wt[pass] = g_twgt[mm];
                id[pass] = g_tidx[mm];
            }
            for (int cg = 0; cg < 8; cg++) {
                int nq   = tap * 8 + cg;
                int nbuf = nq & 1;
                if (nq + 1 < NCHUNK) {
                    const char* pA = (const char*)(g_wA + (nq + 1) * 2048);
                    asm volatile("prefetch.global.L1 [%0];" :: "l"(pA + gtid * 256));
                    asm volatile("prefetch.global.L1 [%0];" :: "l"(pA + gtid * 256 + 128));
                }
                int cc = cg * 32 + gl8 * 4;
                #pragma unroll
                for (int pass = 0; pass < 4; pass++) {
                    int pp = gpx + pass * 16;
                    float4 t0 = __ldg(xb4 + ((id[pass].x + cc) >> 2));
                    float4 t1 = __ldg(xb4 + ((id[pass].y + cc) >> 2));
                    float4 t2 = __ldg(xb4 + ((id[pass].z + cc) >> 2));
                    float4 t3 = __ldg(xb4 + ((id[pass].w + cc) >> 2));
                    float4 wv = wt[pass];
                    float4 v;
                    v.x = wv.x * t0.x + wv.y * t1.x + wv.z * t2.x + wv.w * t3.x;
                    v.y = wv.x * t0.y + wv.y * t1.y + wv.z * t2.y + wv.w * t3.y;
                    v.z = wv.x * t0.z + wv.y * t1.z + wv.z * t2.z + wv.w * t3.z;
                    v.w = wv.x * t0.w + wv.y * t1.w + wv.z * t2.w + wv.w * t3.w;
                    uint32_t h01 = pack_bf16(v.x, v.y);
                    uint32_t h23 = pack_bf16(v.z, v.w);
                    __nv_bfloat162 hh01 = *(__nv_bfloat162*)&h01;
                    __nv_bfloat162 hh23 = *(__nv_bfloat162*)&h23;
                    float lx = v.x - __bfloat162float(hh01.x);
                    float ly = v.y - __bfloat162float(hh01.y);
                    float lz = v.z - __bfloat162float(hh23.x);
                    float lw = v.w - __bfloat162float(hh23.y);
                    int word = pp * BROW + gl8 * 2;
                    *(uint2*)&sB[nbuf][0][word] = make_uint2(h01, h23);
                    *(uint2*)&sB[nbuf][1][word] =
                        make_uint2(pack_bf16(lx, ly), pack_bf16(lz, lw));
                }
                __syncthreads();
            }
        }
        __syncthreads();
    } else {
        // ================= mma warps =================
        int wm = wid >> 1, wn = wid & 1;

        float acc[4][4][4];
        #pragma unroll
        for (int i = 0; i < 4; i++)
            #pragma unroll
            for (int j = 0; j < 4; j++)
                #pragma unroll
                for (int r = 0; r < 4; r++) acc[i][j][r] = 0.f;

        int mat = lane >> 3, mrow = lane & 7;
        int jd  = mat >> 1, kh = mat & 1;
        uint32_t lmB = ((wn * 32 + jd * 8 + mrow) * BROW + kh * 4) * 4;

        for (int q = 0; q < NCHUNK; q++) {
            __syncthreads();
            int buf = q & 1;
            uint32_t bH = (uint32_t)__cvta_generic_to_shared(&sB[buf][0][0]);
            uint32_t bL = (uint32_t)__cvta_generic_to_shared(&sB[buf][1][0]);

            #pragma unroll
            for (int s = 0; s < 2; s++) {
                uint32_t soff = (uint32_t)(s * 32);
                uint32_t Bh[8], Bl[8];
                ldsm4(Bh + 0, bH + lmB + soff);
                ldsm4(Bh + 4, bH + lmB + soff + (uint32_t)(16 * BROW * 4));
                ldsm4(Bl + 0, bL + lmB + soff);
                ldsm4(Bl + 4, bL + lmB + soff + (uint32_t)(16 * BROW * 4));
                // issue ALL A loads up front; latency hides under terms 1-2
                uint4 Ah[4], Al[4];
                #pragma unroll
                for (int i = 0; i < 4; i++) {
                    Ah[i] = __ldg(&g_wA[(((q * 2 + 0) * 16 + wm * 4 + i) * 2 + s) * 32 + lane]);
                    Al[i] = __ldg(&g_wA[(((q * 2 + 1) * 16 + wm * 4 + i) * 2 + s) * 32 + lane]);
                }
                #pragma unroll
                for (int i = 0; i < 4; i++)
                    #pragma unroll
                    for (int j = 0; j < 4; j++)
                        mma16816(acc[i][j], (const uint32_t*)&Ah[i], Bh + 2 * j);
                #pragma unroll
                for (int i = 0; i < 4; i++)
                    #pragma unroll
                    for (int j = 0; j < 4; j++)
                        mma16816(acc[i][j], (const uint32_t*)&Ah[i], Bl + 2 * j);
                #pragma unroll
                for (int i = 0; i < 4; i++)
                    #pragma unroll
                    for (int j = 0; j < 4; j++)
                        mma16816(acc[i][j], (const uint32_t*)&Al[i], Bh + 2 * j);
            }
        }
        __syncthreads();

        int q_ = lane >> 2, t_ = lane & 3;
        #pragma unroll
        for (int i = 0; i < 4; i++) {
            int o0 = wm * 64 + i * 16 + q_;
            float bias0 = __ldg(cb + o0);
            float bias1 = __ldg(cb + o0 + 8);
            float* r0 = out + (size_t)(b * COUT + o0) * HW + hw0 + wn * 32;
            float* r1 = out + (size_t)(b * COUT + o0 + 8) * HW + hw0 + wn * 32;
            #pragma unroll
            for (int j = 0; j < 4; j++) {
                float2 s0, s1;
                s0.x = acc[i][j][0] + bias0; s0.y = acc[i][j][1] + bias0;
                s1.x = acc[i][j][2] + bias1; s1.y = acc[i][j][3] + bias1;
                *(float2*)(r0 + j * 8 + t_ * 2) = s0;
                *(float2*)(r1 + j * 8 + t_ * 2) = s1;
            }
        }
    }
}

// ---------------- launch -----------------------------------------------------
extern "C" void kernel_launch(void* const* d_in, const int* in_sizes, int n_in,
                              void* d_out, int out_size) {
    const float* x  = (const float*)d_in[0];
    const float* ow = (const float*)d_in[1];
    const float* ob = (const float*)d_in[2];
    const float* cw = (const float*)d_in[3];
    const float* cb = (const float*)d_in[4];
    float* out      = (float*)d_out;

    // merged transpose + weight prep (independent work, one launch)
    k_tp_prep<<<TP_BLOCKS + WA_BLOCKS + 72, 256>>>(x, ow, cw);
    k_offset<<<B_ * (HW / 64), 256>>>(ob);
    k_main<<<B_ * (HW / 64), 384>>>(cb, out);
}

// round 16
// speedup vs baseline: 1.0433x; 1.0249x over previous
#include <cuda_runtime.h>
#include <cuda_bf16.h>
#include <cstdint>

#define B_    4
#define C_    256
#define H_    80
#define W_    80
#define HW    6400
#define K2    9
#define KDIM  2304
#define COUT  256
#define NCHUNK 72          // 9 taps * 8 channel-groups of 32
#define BROW  20           // u32 words per row (80 B stride, 16 used)

// ---------------- device scratch ----------------
__device__ float    g_xnhwc[B_ * HW * C_];          // x in NHWC
__device__ uint4    g_wA[NCHUNK * 2 * 16 * 2 * 32]; // conv-w fragments (hi/lo)
__device__ uint4    g_oA[NCHUNK * 2 * 2 * 2 * 32];  // offset-w fragments (hi/lo, M=32)
__device__ float4   g_twgt[B_ * K2 * HW];           // bilinear weights * validity
__device__ int4     g_tidx[B_ * K2 * HW];           // clamped NHWC bases

// ---------------- mma helpers ----------------
__device__ __forceinline__ void mma16816(float* d, const uint32_t* a, const uint32_t* b) {
    asm volatile(
        "mma.sync.aligned.m16n8k16.row.col.f32.bf16.bf16.f32 "
        "{%0,%1,%2,%3}, {%4,%5,%6,%7}, {%8,%9}, {%0,%1,%2,%3};"
        : "+f"(d[0]), "+f"(d[1]), "+f"(d[2]), "+f"(d[3])
        : "r"(a[0]), "r"(a[1]), "r"(a[2]), "r"(a[3]), "r"(b[0]), "r"(b[1]));
}

__device__ __forceinline__ void ldsm4(uint32_t* r, uint32_t addr) {
    asm volatile("ldmatrix.sync.aligned.m8n8.x4.shared.b16 {%0,%1,%2,%3}, [%4];"
                 : "=r"(r[0]), "=r"(r[1]), "=r"(r[2]), "=r"(r[3]) : "r"(addr));
}

__device__ __forceinline__ uint32_t pack_bf16(float lo_v, float hi_v) {
    __nv_bfloat162 h;
    h.x = __float2bfloat16(lo_v);
    h.y = __float2bfloat16(hi_v);
    return *(uint32_t*)&h;
}

// ---------------- kernel 1: merged NCHW->NHWC transpose + weight prep ------
#define TP_BLOCKS 6400
#define WA_BLOCKS 576   // 147456 / 256
__global__ void __launch_bounds__(256) k_tp_prep(const float* __restrict__ x,
                                                 const float* __restrict__ ow,
                                                 const float* __restrict__ cw) {
    int blk = blockIdx.x;
    if (blk < TP_BLOCKS) {
        __shared__ float tile[32][33];
        int hwb = blk % 200;
        int cb_ = (blk / 200) & 7;
        int b   = blk / 1600;
        int hw0 = hwb * 32;
        int c0  = cb_ * 32;
        int tx = threadIdx.x & 31, ty = threadIdx.x >> 5;
        const float* xb = x + b * C_ * HW;
        #pragma unroll
        for (int i = 0; i < 32; i += 8)
            tile[ty + i][tx] = xb[(c0 + ty + i) * HW + hw0 + tx];
        __syncthreads();
        float* ob = g_xnhwc + b * HW * C_;
        #pragma unroll
        for (int i = 0; i < 32; i += 8)
            ob[(hw0 + ty + i) * C_ + c0 + tx] = tile[tx][ty + i];
    } else if (blk < TP_BLOCKS + WA_BLOCKS) {
        int e = (blk - TP_BLOCKS) * 256 + threadIdx.x;
        int lane = e & 31;
        int s    = (e >> 5) & 1;
        int mt   = (e >> 6) & 15;
        int term = (e >> 10) & 1;
        int q    = e >> 11;
        int tap   = q >> 3;
        int cbase = (q & 7) * 32;
        uint32_t r[4];
        #pragma unroll
        for (int rr = 0; rr < 4; rr++) {
            int m  = mt * 16 + (lane >> 2) + ((rr & 1) << 3);
            int kl = s * 16 + (lane & 3) * 2 + ((rr >> 1) << 3);
            float w0 = __ldg(cw + m * KDIM + (cbase + kl) * 9 + tap);
            float w1 = __ldg(cw + m * KDIM + (cbase + kl + 1) * 9 + tap);
            if (term) {
                w0 -= __bfloat162float(__float2bfloat16(w0));
                w1 -= __bfloat162float(__float2bfloat16(w1));
            }
            r[rr] = pack_bf16(w0, w1);
        }
        g_wA[e] = make_uint4(r[0], r[1], r[2], r[3]);
    } else {
        int e = (blk - TP_BLOCKS - WA_BLOCKS) * 256 + threadIdx.x;
        if (e < NCHUNK * 2 * 2 * 2 * 32) {
            int lane = e & 31;
            int s    = (e >> 5) & 1;
            int mt   = (e >> 6) & 1;
            int term = (e >> 7) & 1;
            int q    = e >> 8;
            int tap   = q >> 3;
            int cbase = (q & 7) * 32;
            uint32_t r[4];
            #pragma unroll
            for (int rr = 0; rr < 4; rr++) {
                int m  = mt * 16 + (lane >> 2) + ((rr & 1) << 3);
                int kl = s * 16 + (lane & 3) * 2 + ((rr >> 1) << 3);
                float w0 = 0.f, w1 = 0.f;
                if (m < 18) {
                    w0 = __ldg(ow + m * KDIM + (cbase + kl) * 9 + tap);
                    w1 = __ldg(ow + m * KDIM + (cbase + kl + 1) * 9 + tap);
                }
                if (term) {
                    w0 -= __bfloat162float(__float2bfloat16(w0));
                    w1 -= __bfloat162float(__float2bfloat16(w1));
                }
                r[rr] = pack_bf16(w0, w1);
            }
            g_oA[e] = make_uint4(r[0], r[1], r[2], r[3]);
        }
    }
}

// ---------------- kernel 2: offset conv via mma, software-pipelined --------
// Double-buffered sB, ONE __syncthreads per chunk: store chunk q, issue
// chunk q+1 LDGs, sync, mma(q) while q+1 loads are in flight.
__global__ void __launch_bounds__(256) k_offset(const float* __restrict__ off_b) {
    __shared__ uint32_t sB[2][2][64 * BROW];   // [buf][term][px*20+word]
    __shared__ float offs[64][19];

    int tid  = threadIdx.x;
    int wid  = tid >> 5, lane = tid & 31;
    int blk  = blockIdx.x;                 // 0..399
    int b    = blk / (HW / 64);
    int hw0  = (blk % (HW / 64)) * 64;

    const float4* xb4 = (const float4*)(g_xnhwc + (size_t)b * HW * C_);

    int px = tid >> 2, cq = tid & 3;
    int gpx = hw0 + px;
    int py = gpx / W_, pxx = gpx % W_;

    int mat = lane >> 3, mrow = lane & 7;
    int jd  = mat >> 1, kh = mat & 1;
    uint32_t lmB = (uint32_t)(((wid * 16 + jd * 8 + mrow) * BROW + kh * 4) * 4);

    float acc[2][2][4];
    #pragma unroll
    for (int mt = 0; mt < 2; mt++)
        #pragma unroll
        for (int j = 0; j < 2; j++)
            #pragma unroll
            for (int r = 0; r < 4; r++) acc[mt][j][r] = 0.f;

    // gather for one chunk: 2 float4 (8 channels)
    auto gather = [&](int q, float4* v) {
        int tap = q >> 3, cg = q & 7;
        int dy = tap / 3 - 1, dx = tap % 3 - 1;
        int ny = py + dy, nx = pxx + dx;
        bool valid = (ny >= 0 && ny < H_ && nx >= 0 && nx < W_);
        const float4* src = xb4 + (((ny * W_ + nx) * C_ + cg * 32 + cq * 8) >> 2);
        v[0] = valid ? __ldg(src + 0) : make_float4(0.f, 0.f, 0.f, 0.f);
        v[1] = valid ? __ldg(src + 1) : make_float4(0.f, 0.f, 0.f, 0.f);
    };

    float4 v[2], v2[2];
    gather(0, v);

    for (int q = 0; q < NCHUNK; q++) {
        int buf = q & 1;
        // store chunk q (from registers) to sB[buf]
        #pragma unroll
        for (int cc = 0; cc < 2; cc++) {
            float4 w = v[cc];
            uint32_t h01 = pack_bf16(w.x, w.y);
            uint32_t h23 = pack_bf16(w.z, w.w);
            __nv_bfloat162 hh01 = *(__nv_bfloat162*)&h01;
            __nv_bfloat162 hh23 = *(__nv_bfloat162*)&h23;
            float lx = w.x - __bfloat162float(hh01.x);
            float ly = w.y - __bfloat162float(hh01.y);
            float lz = w.z - __bfloat162float(hh23.x);
            float lw = w.w - __bfloat162float(hh23.y);
            int word = px * BROW + cq * 4 + cc * 2;
            *(uint2*)&sB[buf][0][word] = make_uint2(h01, h23);
            *(uint2*)&sB[buf][1][word] = make_uint2(pack_bf16(lx, ly), pack_bf16(lz, lw));
        }
        // issue next chunk's LDGs (latency hides under mma below)
        if (q + 1 < NCHUNK) gather(q + 1, v2);
        __syncthreads();

        if (wid < 4) {
            uint32_t sb0 = (uint32_t)__cvta_generic_to_shared(&sB[buf][0][0]);
            uint32_t sb1 = (uint32_t)__cvta_generic_to_shared(&sB[buf][1][0]);
            #pragma unroll
            for (int s = 0; s < 2; s++) {
                uint32_t soff = (uint32_t)(s * 32);
                uint32_t Bh[4], Bl[4];
                ldsm4(Bh, sb0 + lmB + soff);
                ldsm4(Bl, sb1 + lmB + soff);
                uint4 Ah[2], Al[2];
                #pragma unroll
                for (int mt = 0; mt < 2; mt++) {
                    Ah[mt] = __ldg(&g_oA[(((q * 2 + 0) * 2 + mt) * 2 + s) * 32 + lane]);
                    Al[mt] = __ldg(&g_oA[(((q * 2 + 1) * 2 + mt) * 2 + s) * 32 + lane]);
                }
                #pragma unroll
                for (int mt = 0; mt < 2; mt++)
                    #pragma unroll
                    for (int j = 0; j < 2; j++) {
                        mma16816(acc[mt][j], (const uint32_t*)&Ah[mt], Bh + 2 * j);
                        mma16816(acc[mt][j], (const uint32_t*)&Ah[mt], Bl + 2 * j);
                        mma16816(acc[mt][j], (const uint32_t*)&Al[mt], Bh + 2 * j);
                    }
            }
        }
        v[0] = v2[0]; v[1] = v2[1];
    }
    __syncthreads();

    if (wid < 4) {
        #pragma unroll
        for (int mt = 0; mt < 2; mt++)
            #pragma unroll
            for (int j = 0; j < 2; j++)
                #pragma unroll
                for (int r = 0; r < 4; r++) {
                    int oc = mt * 16 + (lane >> 2) + ((r >> 1) << 3);
                    int pc = wid * 16 + j * 8 + (lane & 3) * 2 + (r & 1);
                    if (oc < 18)
                        offs[pc][oc] = acc[mt][j][r] + __ldg(off_b + oc);
                }
    }
    __syncthreads();

    for (int u = tid; u < 64 * 9; u += 256) {
        int l = u / 9, k = u % 9;
        float dyo = offs[l][2 * k], dxo = offs[l][2 * k + 1];
        int pp = hw0 + l;
        int yy = pp / W_, xx = pp % W_;
        float fy = (float)(yy + k / 3 - 1) + dyo;
        float fx = (float)(xx + k % 3 - 1) + dxo;
        float y0f = floorf(fy), x0f = floorf(fx);
        float wy = fy - y0f, wx = fx - x0f;
        int y0 = (int)y0f, x0 = (int)x0f;
        int y1 = y0 + 1,   x1 = x0 + 1;
        float vy0 = (y0 >= 0 && y0 < H_) ? 1.f : 0.f;
        float vy1 = (y1 >= 0 && y1 < H_) ? 1.f : 0.f;
        float vx0 = (x0 >= 0 && x0 < W_) ? 1.f : 0.f;
        float vx1 = (x1 >= 0 && x1 < W_) ? 1.f : 0.f;
        int cy0 = min(max(y0, 0), H_ - 1), cy1 = min(max(y1, 0), H_ - 1);
        int cx0 = min(max(x0, 0), W_ - 1), cx1 = min(max(x1, 0), W_ - 1);
        float4 wt;
        wt.x = (1.f - wy) * (1.f - wx) * vy0 * vx0;
        wt.y = (1.f - wy) * wx         * vy0 * vx1;
        wt.z = wy * (1.f - wx)         * vy1 * vx0;
        wt.w = wy * wx                 * vy1 * vx1;
        int4 id;
        id.x = (cy0 * W_ + cx0) * C_;
        id.y = (cy0 * W_ + cx1) * C_;
        id.z = (cy1 * W_ + cx0) * C_;
        id.w = (cy1 * W_ + cx1) * C_;
        int m = (b * 9 + k) * HW + pp;
        g_twgt[m] = wt;
        g_tidx[m] = id;
    }
}

// ---------------- kernel 3: warp-specialized main GEMM (R12 best) ----------
__global__ void __launch_bounds__(384, 1) k_main(const float* __restrict__ cb,
                                                 float* __restrict__ out) {
    __shared__ uint32_t sB[2][2][64 * BROW];   // [buf][term][pixel*20 + word]

    int tid  = threadIdx.x;
    int wid  = tid >> 5, lane = tid & 31;
    int blk  = blockIdx.x;                   // 0..399
    int b    = blk / (HW / 64);
    int hw0  = (blk % (HW / 64)) * 64;
    int b9   = b * 9;

    const float4* xb4 = (const float4*)(g_xnhwc + (size_t)b * HW * C_);

    if (wid >= 8) {
        // ================= producer warps =================
        int gtid = tid - 256;                // 0..127
        int gl8  = gtid & 7;
        int gpx  = gtid >> 3;                // 0..15
        for (int tap = 0; tap < 9; tap++) {
            int mmb = (b9 + tap) * HW + hw0;
            float4 wt[4]; int4 id[4];
            #pragma unroll
            for (int pass = 0; pass < 4; pass++) {
                int mm = mmb + gpx + pass * 16;
                wt[pass] = g_twgt[mm];
                id[pass] = g_tidx[mm];
            }
            for (int cg = 0; cg < 8; cg++) {
                int nq   = tap * 8 + cg;
                int nbuf = nq & 1;
                if (nq + 1 < NCHUNK) {
                    const char* pA = (const char*)(g_wA + (nq + 1) * 2048);
                    asm volatile("prefetch.global.L1 [%0];" :: "l"(pA + gtid * 256));
                    asm volatile("prefetch.global.L1 [%0];" :: "l"(pA + gtid * 256 + 128));
                }
                int cc = cg * 32 + gl8 * 4;
                #pragma unroll
                for (int pass = 0; pass < 4; pass++) {
                    int pp = gpx + pass * 16;
                    float4 t0 = __ldg(xb4 + ((id[pass].x + cc) >> 2));
                    float4 t1 = __ldg(xb4 + ((id[pass].y + cc) >> 2));
                    float4 t2 = __ldg(xb4 + ((id[pass].z + cc) >> 2));
                    float4 t3 = __ldg(xb4 + ((id[pass].w + cc) >> 2));
                    float4 wv = wt[pass];
                    float4 v;
                    v.x = wv.x * t0.x + wv.y * t1.x + wv.z * t2.x + wv.w * t3.x;
                    v.y = wv.x * t0.y + wv.y * t1.y + wv.z * t2.y + wv.w * t3.y;
                    v.z = wv.x * t0.z + wv.y * t1.z + wv.z * t2.z + wv.w * t3.z;
                    v.w = wv.x * t0.w + wv.y * t1.w + wv.z * t2.w + wv.w * t3.w;
                    uint32_t h01 = pack_bf16(v.x, v.y);
                    uint32_t h23 = pack_bf16(v.z, v.w);
                    __nv_bfloat162 hh01 = *(__nv_bfloat162*)&h01;
                    __nv_bfloat162 hh23 = *(__nv_bfloat162*)&h23;
                    float lx = v.x - __bfloat162float(hh01.x);
                    float ly = v.y - __bfloat162float(hh01.y);
                    float lz = v.z - __bfloat162float(hh23.x);
                    float lw = v.w - __bfloat162float(hh23.y);
                    int word = pp * BROW + gl8 * 2;
                    *(uint2*)&sB[nbuf][0][word] = make_uint2(h01, h23);
                    *(uint2*)&sB[nbuf][1][word] =
                        make_uint2(pack_bf16(lx, ly), pack_bf16(lz, lw));
                }
                __syncthreads();
            }
        }
        __syncthreads();
    } else {
        // ================= mma warps =================
        int wm = wid >> 1, wn = wid & 1;

        float acc[4][4][4];
        #pragma unroll
        for (int i = 0; i < 4; i++)
            #pragma unroll
            for (int j = 0; j < 4; j++)
                #pragma unroll
                for (int r = 0; r < 4; r++) acc[i][j][r] = 0.f;

        int mat = lane >> 3, mrow = lane & 7;
        int jd  = mat >> 1, kh = mat & 1;
        uint32_t lmB = ((wn * 32 + jd * 8 + mrow) * BROW + kh * 4) * 4;

        for (int q = 0; q < NCHUNK; q++) {
            __syncthreads();
            int buf = q & 1;
            uint32_t bH = (uint32_t)__cvta_generic_to_shared(&sB[buf][0][0]);
            uint32_t bL = (uint32_t)__cvta_generic_to_shared(&sB[buf][1][0]);

            #pragma unroll
            for (int s = 0; s < 2; s++) {
                uint32_t soff = (uint32_t)(s * 32);
                uint32_t Bh[8], Bl[8];
                ldsm4(Bh + 0, bH + lmB + soff);
                ldsm4(Bh + 4, bH + lmB + soff + (uint32_t)(16 * BROW * 4));
                ldsm4(Bl + 0, bL + lmB + soff);
                ldsm4(Bl + 4, bL + lmB + soff + (uint32_t)(16 * BROW * 4));
                uint4 Ah[4];
                #pragma unroll
                for (int i = 0; i < 4; i++)
                    Ah[i] = __ldg(&g_wA[(((q * 2 + 0) * 16 + wm * 4 + i) * 2 + s) * 32 + lane]);
                #pragma unroll
                for (int i = 0; i < 4; i++)
                    #pragma unroll
                    for (int j = 0; j < 4; j++)
                        mma16816(acc[i][j], (const uint32_t*)&Ah[i], Bh + 2 * j);
                #pragma unroll
                for (int i = 0; i < 4; i++)
                    #pragma unroll
                    for (int j = 0; j < 4; j++)
                        mma16816(acc[i][j], (const uint32_t*)&Ah[i], Bl + 2 * j);
                #pragma unroll
                for (int i = 0; i < 4; i++) {
                    uint4 Al = __ldg(&g_wA[(((q * 2 + 1) * 16 + wm * 4 + i) * 2 + s) * 32 + lane]);
                    #pragma unroll
                    for (int j = 0; j < 4; j++)
                        mma16816(acc[i][j], (const uint32_t*)&Al, Bh + 2 * j);
                }
            }
        }
        __syncthreads();

        int q_ = lane >> 2, t_ = lane & 3;
        #pragma unroll
        for (int i = 0; i < 4; i++) {
            int o0 = wm * 64 + i * 16 + q_;
            float bias0 = __ldg(cb + o0);
            float bias1 = __ldg(cb + o0 + 8);
            float* r0 = out + (size_t)(b * COUT + o0) * HW + hw0 + wn * 32;
            float* r1 = out + (size_t)(b * COUT + o0 + 8) * HW + hw0 + wn * 32;
            #pragma unroll
            for (int j = 0; j < 4; j++) {
                float2 s0, s1;
                s0.x = acc[i][j][0] + bias0; s0.y = acc[i][j][1] + bias0;
                s1.x = acc[i][j][2] + bias1; s1.y = acc[i][j][3] + bias1;
                *(float2*)(r0 + j * 8 + t_ * 2) = s0;
                *(float2*)(r1 + j * 8 + t_ * 2) = s1;
            }
        }
    }
}

// ---------------- launch -----------------------------------------------------
extern "C" void kernel_launch(void* const* d_in, const int* in_sizes, int n_in,
                              void* d_out, int out_size) {
    const float* x  = (const float*)d_in[0];
    const float* ow = (const float*)d_in[1];
    const float* ob = (const float*)d_in[2];
    const float* cw = (const float*)d_in[3];
    const float* cb = (const float*)d_in[4];
    float* out      = (float*)d_out;

    k_tp_prep<<<TP_BLOCKS + WA_BLOCKS + 72, 256>>>(x, ow, cw);
    k_offset<<<B_ * (HW / 64), 256>>>(ob);
    k_main<<<B_ * (HW / 64), 384>>>(cb, out);
}